// round 3
// baseline (speedup 1.0000x reference)
#include <cuda_runtime.h>
#include <cstdint>
#include <cstddef>

// Problem dims
#define HD    512
#define BATCH 1024
#define TSEQ  512
#define PLEN  96
#define DIN   32

// Persistent-kernel config
#define NCTA  128      // <= SM count: all CTAs co-resident, grid barrier is safe
#define BM    64       // batch rows per CTA tile
#define BN    64       // hidden cols per CTA tile (x3 gates)
#define BK    16       // k-slice

// -------- scratch (static device globals; no allocation allowed) --------
__device__ float    g_h1[2][BATCH * HD];
__device__ float    g_h2[2][BATCH * HD];
__device__ float    g_y[BATCH];
__device__ unsigned g_cnt;   // zero-initialized
__device__ unsigned g_gen;   // zero-initialized (generation counter; wraps safely)

// -------- packed fp32x2 helpers (Blackwell FFMA2 path, PTX-only) --------
#define PACKF2(o, l, h)   asm("mov.b64 %0,{%1,%2};" : "=l"(o) : "r"(l), "r"(h))
#define UNPACKF2(l, h, i) asm("mov.b64 {%0,%1},%2;" : "=r"(l), "=r"(h) : "l"(i))
#define FMAF2(c, a, b)    asm("fma.rn.f32x2 %0,%1,%2,%0;" : "+l"(c) : "l"(a), "l"(b))

struct SmemT {
    float  a[BK][BM + 4];     // [k][m]; row = 272B (16B multiple) so float4 reads align
    float2 b[BK][3][32];      // [k][gate][col_pair] = (col 2p, col 2p+1)
};

// ---------------------------------------------------------------------------
// Grid-wide barrier. All 128 CTAs are resident (grid <= SMs), so spinning is
// deadlock-free. Release: syncthreads -> thread0 fence.gpu -> atomic arrive.
// Acquire: spin on generation -> fence.gpu -> syncthreads.
// ---------------------------------------------------------------------------
__device__ __forceinline__ void gbar()
{
    __syncthreads();
    if (threadIdx.x == 0) {
        __threadfence();                                   // release all CTA writes
        unsigned gen = *(volatile unsigned*)&g_gen;        // read before arriving
        unsigned t = atomicAdd(&g_cnt, 1u);
        if (t == NCTA - 1) {
            *(volatile unsigned*)&g_cnt = 0;
            __threadfence();
            *(volatile unsigned*)&g_gen = gen + 1;
        } else {
            while (*(volatile unsigned*)&g_gen == gen) __nanosleep(32);
        }
        __threadfence();                                   // acquire (flushes L1)
    }
    __syncthreads();
}

// ---------------------------------------------------------------------------
// K-tiled GEMM accumulating 3 gate columns into f32x2 accumulators.
//   aR/aZ/aN[row][pairhalf] over cols (n0+2tx, n0+2tx+1) and (n0+32+2tx, +33).
// ---------------------------------------------------------------------------
__device__ __forceinline__ void gemm_acc(
    SmemT* sm, const float* __restrict__ A, int ldA,
    const float* __restrict__ W, int ldW, int K,
    int m0, int n0, int tid, int tx, int ty,
    unsigned long long (*aR)[2], unsigned long long (*aZ)[2],
    unsigned long long (*aN)[2])
{
    for (int kt = 0; kt < K; kt += BK) {
        __syncthreads();
        // A tile: 64 rows x 16 k (one float4/thread), stored transposed
        {
            const int r = tid >> 2, c4 = (tid & 3) << 2;
            const float4 v = *reinterpret_cast<const float4*>(
                A + (size_t)(m0 + r) * ldA + kt + c4);
            sm->a[c4 + 0][r] = v.x;
            sm->a[c4 + 1][r] = v.y;
            sm->a[c4 + 2][r] = v.z;
            sm->a[c4 + 3][r] = v.w;
        }
        // W tile: 3 gates x 64 cols x 16 k -> float2 col-pairs
#pragma unroll
        for (int ii = 0; ii < 3; ii++) {
            const int idx = tid + ii * 256;
            const int u = idx >> 2, c4 = (idx & 3) << 2;
            const int g = u >> 6, cc = u & 63, pp = cc >> 1, half = cc & 1;
            const float4 v = *reinterpret_cast<const float4*>(
                W + (size_t)(g * HD + n0 + cc) * ldW + kt + c4);
            reinterpret_cast<float*>(&sm->b[c4 + 0][g][pp])[half] = v.x;
            reinterpret_cast<float*>(&sm->b[c4 + 1][g][pp])[half] = v.y;
            reinterpret_cast<float*>(&sm->b[c4 + 2][g][pp])[half] = v.z;
            reinterpret_cast<float*>(&sm->b[c4 + 3][g][pp])[half] = v.w;
        }
        __syncthreads();
#pragma unroll
        for (int k = 0; k < BK; k++) {
            const float4 av = *reinterpret_cast<const float4*>(&sm->a[k][ty << 2]);
            unsigned long long a2[4];
            { uint32_t u0 = __float_as_uint(av.x); PACKF2(a2[0], u0, u0); }
            { uint32_t u1 = __float_as_uint(av.y); PACKF2(a2[1], u1, u1); }
            { uint32_t u2 = __float_as_uint(av.z); PACKF2(a2[2], u2, u2); }
            { uint32_t u3 = __float_as_uint(av.w); PACKF2(a2[3], u3, u3); }
            const unsigned long long b0a = *reinterpret_cast<unsigned long long*>(&sm->b[k][0][tx]);
            const unsigned long long b0b = *reinterpret_cast<unsigned long long*>(&sm->b[k][0][tx + 16]);
            const unsigned long long b1a = *reinterpret_cast<unsigned long long*>(&sm->b[k][1][tx]);
            const unsigned long long b1b = *reinterpret_cast<unsigned long long*>(&sm->b[k][1][tx + 16]);
            const unsigned long long b2a = *reinterpret_cast<unsigned long long*>(&sm->b[k][2][tx]);
            const unsigned long long b2b = *reinterpret_cast<unsigned long long*>(&sm->b[k][2][tx + 16]);
#pragma unroll
            for (int i = 0; i < 4; i++) {
                FMAF2(aR[i][0], a2[i], b0a); FMAF2(aR[i][1], a2[i], b0b);
                FMAF2(aZ[i][0], a2[i], b1a); FMAF2(aZ[i][1], a2[i], b1b);
                FMAF2(aN[i][0], a2[i], b2a); FMAF2(aN[i][1], a2[i], b2b);
            }
        }
    }
}

// ---------------------------------------------------------------------------
// Persistent kernel: entire encoder (512 steps) + decoder (96 steps).
// CTA tile: (blockIdx.x & 15) -> 64 batch rows, (blockIdx.x >> 4) -> 64 h cols.
// ---------------------------------------------------------------------------
__global__ void __launch_bounds__(256, 1) gru_persistent(
    const float* __restrict__ x,
    const float* __restrict__ eWih0, const float* __restrict__ eWhh0,
    const float* __restrict__ ebih0, const float* __restrict__ ebhh0,
    const float* __restrict__ eWih1, const float* __restrict__ eWhh1,
    const float* __restrict__ ebih1, const float* __restrict__ ebhh1,
    const float* __restrict__ dWih0, const float* __restrict__ dWhh0,
    const float* __restrict__ dbih0, const float* __restrict__ dbhh0,
    const float* __restrict__ dWih1, const float* __restrict__ dWhh1,
    const float* __restrict__ dbih1, const float* __restrict__ dbhh1,
    const float* __restrict__ outW,  const float* __restrict__ outb,
    const float* __restrict__ dstart, float* __restrict__ out)
{
    __shared__ SmemT sm;
    const int tid = threadIdx.x;
    const int tx = tid & 15, ty = tid >> 4;
    const int m0 = (blockIdx.x & 15) * BM;
    const int n0 = (blockIdx.x >> 4) * BN;

    // ---- init: zero parity-0 states, y = dec_start ----
    for (int i = blockIdx.x * 256 + tid; i < BATCH * HD; i += NCTA * 256) {
        g_h1[0][i] = 0.f; g_h2[0][i] = 0.f;
    }
    for (int i = blockIdx.x * 256 + tid; i < BATCH; i += NCTA * 256)
        g_y[i] = dstart[0];
    gbar();

    // ---- fused GRU cell: hidden GEMM + input GEMM (+scalar path) + gates ----
    auto cell = [&](const float* __restrict__ hprev, float* __restrict__ hout,
                    const float* __restrict__ Whh, const float* __restrict__ bhh,
                    const float* __restrict__ Ax, int ldx, int K2,
                    const float* __restrict__ Wih, int ldw,
                    const float* __restrict__ bih)
    {
        unsigned long long aR[4][2], aZ[4][2], aNH[4][2], aNI[4][2];
#pragma unroll
        for (int i = 0; i < 4; i++)
#pragma unroll
            for (int j = 0; j < 2; j++) { aR[i][j] = 0; aZ[i][j] = 0; aNH[i][j] = 0; aNI[i][j] = 0; }

        gemm_acc(&sm, hprev, HD, Whh, HD, HD, m0, n0, tid, tx, ty, aR, aZ, aNH);
        if (K2 >= BK)
            gemm_acc(&sm, Ax, ldx, Wih, ldw, K2, m0, n0, tid, tx, ty, aR, aZ, aNI);

#pragma unroll
        for (int i = 0; i < 4; i++) {
            const int m = m0 + (ty << 2) + i;
            const float yy = (K2 < BK) ? Ax[m] : 0.f;
#pragma unroll
            for (int j = 0; j < 2; j++) {
                const int cb = n0 + 2 * tx + (j ? 32 : 0);
                uint32_t l, h;
                float rv[2], zv[2], nh[2], ni[2];
                UNPACKF2(l, h, aR[i][j]);  rv[0] = __uint_as_float(l); rv[1] = __uint_as_float(h);
                UNPACKF2(l, h, aZ[i][j]);  zv[0] = __uint_as_float(l); zv[1] = __uint_as_float(h);
                UNPACKF2(l, h, aNH[i][j]); nh[0] = __uint_as_float(l); nh[1] = __uint_as_float(h);
                UNPACKF2(l, h, aNI[i][j]); ni[0] = __uint_as_float(l); ni[1] = __uint_as_float(h);
#pragma unroll
                for (int e = 0; e < 2; e++) {
                    const int col = cb + e;
                    float gr = rv[e], gz = zv[e], gn = ni[e];
                    if (K2 < BK) {   // decoder layer0: gi = y[b] * Wih[:,0]
                        gr += yy * Wih[col];
                        gz += yy * Wih[HD + col];
                        gn += yy * Wih[2 * HD + col];
                    }
                    const float rr = gr + bih[col] + bhh[col];
                    const float zz = gz + bih[HD + col] + bhh[HD + col];
                    const float r = 1.f / (1.f + expf(-rr));
                    const float z = 1.f / (1.f + expf(-zz));
                    const float n = tanhf(gn + bih[2 * HD + col] +
                                          r * (nh[e] + bhh[2 * HD + col]));
                    const float hp = hprev[(size_t)m * HD + col];
                    hout[(size_t)m * HD + col] = (1.f - z) * n + z * hp;
                }
            }
        }
    };

    int p = 0;
    // ---------------- encoder: 512 steps ----------------
    for (int t = 0; t < TSEQ; t++) {
        cell(g_h1[p], g_h1[1 - p], eWhh0, ebhh0,
             x + (size_t)t * DIN, TSEQ * DIN, DIN, eWih0, DIN, ebih0);
        gbar();
        cell(g_h2[p], g_h2[1 - p], eWhh1, ebhh1,
             g_h1[1 - p], HD, HD, eWih1, HD, ebih1);
        gbar();
        p ^= 1;
    }
    // ---------------- decoder: 96 steps ----------------
    for (int s = 0; s < PLEN; s++) {
        cell(g_h1[p], g_h1[1 - p], dWhh0, dbhh0,
             g_y, 1, 1, dWih0, 1, dbih0);
        gbar();
        cell(g_h2[p], g_h2[1 - p], dWhh1, dbhh1,
             g_h1[1 - p], HD, HD, dWih1, HD, dbih1);
        gbar();
        // projection: 8 rows per CTA, one warp each
        {
            const int w = tid >> 5, lane = tid & 31;
            const int row = blockIdx.x * 8 + w;
            const float* hr = g_h2[1 - p] + (size_t)row * HD;
            float ssum = 0.f;
#pragma unroll
            for (int q = 0; q < HD / 32; q++)
                ssum += hr[lane + 32 * q] * outW[lane + 32 * q];
#pragma unroll
            for (int o = 16; o > 0; o >>= 1)
                ssum += __shfl_xor_sync(0xffffffffu, ssum, o);
            if (lane == 0) {
                const float v = ssum + outb[0];
                g_y[row] = v;
                out[(size_t)row * PLEN + s] = v;
            }
        }
        gbar();
        p ^= 1;
    }
}

// ---------------------------------------------------------------------------
extern "C" void kernel_launch(void* const* d_in, const int* in_sizes, int n_in,
                              void* d_out, int out_size)
{
    const float* x      = (const float*)d_in[0];
    const float* eWih0  = (const float*)d_in[1];
    const float* eWhh0  = (const float*)d_in[2];
    const float* ebih0  = (const float*)d_in[3];
    const float* ebhh0  = (const float*)d_in[4];
    const float* eWih1  = (const float*)d_in[5];
    const float* eWhh1  = (const float*)d_in[6];
    const float* ebih1  = (const float*)d_in[7];
    const float* ebhh1  = (const float*)d_in[8];
    const float* dWih0  = (const float*)d_in[9];
    const float* dWhh0  = (const float*)d_in[10];
    const float* dbih0  = (const float*)d_in[11];
    const float* dbhh0  = (const float*)d_in[12];
    const float* dWih1  = (const float*)d_in[13];
    const float* dWhh1  = (const float*)d_in[14];
    const float* dbih1  = (const float*)d_in[15];
    const float* dbhh1  = (const float*)d_in[16];
    const float* outW   = (const float*)d_in[17];
    const float* outb   = (const float*)d_in[18];
    const float* dstart = (const float*)d_in[19];
    float* out = (float*)d_out;

    gru_persistent<<<NCTA, 256>>>(
        x,
        eWih0, eWhh0, ebih0, ebhh0,
        eWih1, eWhh1, ebih1, ebhh1,
        dWih0, dWhh0, dbih0, dbhh0,
        dWih1, dWhh1, dbih1, dbhh1,
        outW, outb, dstart, out);
}

// round 5
// speedup vs baseline: 2.5289x; 2.5289x over previous
#include <cuda_runtime.h>
#include <cuda_bf16.h>
#include <cstdint>
#include <cstddef>

// ---------------- problem dims ----------------
#define HD    512
#define BATCH 1024
#define TSEQ  512
#define PLEN  96
#define DIN   32

// ---------------- tiling ----------------
#define NCTA 128
#define MT   8          // m-tiles (BATCH/128)
#define NTL  16         // n-tiles (HD/32)
#define BMR  128        // batch rows per CTA
#define BNR  96         // gate rows of W per CTA (3 gates x 32)
#define KC   64         // k per chunk

#define A_ELE (BMR*KC)  // 8192
#define B_ELE (BNR*KC)  // 6144
#define A_BYT (A_ELE*2) // 16384
#define B_BYT (B_ELE*2) // 12288
#define BUF_BYTES (2*A_BYT + 2*B_BYT)   // 57344
#define SM_TOTAL  (2*BUF_BYTES)         // 114688

// ---------------- device globals (static scratch) ----------------
__device__ float g_h1[2][BATCH*HD];
__device__ float g_h2[2][BATCH*HD];
__device__ __align__(16) __nv_bfloat16 g_h1bf[2][MT][8][2][A_ELE];
__device__ __align__(16) __nv_bfloat16 g_h2bf[2][MT][8][2][A_ELE];
__device__ __align__(16) __nv_bfloat16 g_xbf[TSEQ][MT][A_ELE];     // [xhi|xlo] k64
__device__ __align__(16) __nv_bfloat16 g_w[6][NTL][8][2][B_ELE];   // 0:e0hh 1:e1ih 2:e1hh 3:d0hh 4:d1ih 5:d1hh
__device__ __align__(16) __nv_bfloat16 g_wx[NTL][2][B_ELE];        // enc0 Wih: B1=[Whi|Whi], B2=[Wlo|0]
__device__ float g_br[4][HD], g_bz[4][HD], g_bin[4][HD], g_bhn[4][HD];
__device__ float g_y[BATCH];
__device__ unsigned g_cnt, g_gen;

// ---------------- tile addressing (ldmatrix-friendly swizzle) ----------------
// rows of 64 bf16 (128B); 16B unit XOR-swizzled by row&7 -> conflict-free LDSM.
__host__ __device__ __forceinline__ int offel(int r, int k) {
    return r * 64 + ((((k >> 3) ^ (r & 7)) << 3) | (k & 7));
}

// ---------------- PTX helpers ----------------
__device__ __forceinline__ uint32_t smem_u32(const void* p) {
    uint32_t a;
    asm("{ .reg .u64 t; cvta.to.shared.u64 t, %1; cvt.u32.u64 %0, t; }" : "=r"(a) : "l"(p));
    return a;
}
#define LDSM4(r, addr) asm volatile("ldmatrix.sync.aligned.m8n8.x4.shared.b16 {%0,%1,%2,%3},[%4];" \
    : "=r"((r)[0]), "=r"((r)[1]), "=r"((r)[2]), "=r"((r)[3]) : "r"(addr))
#define LDSM2(r, addr) asm volatile("ldmatrix.sync.aligned.m8n8.x2.shared.b16 {%0,%1},[%2];" \
    : "=r"((r)[0]), "=r"((r)[1]) : "r"(addr))
#define MMAB(d, a, b) asm volatile( \
    "mma.sync.aligned.m16n8k16.row.col.f32.bf16.bf16.f32 {%0,%1,%2,%3},{%4,%5,%6,%7},{%8,%9},{%0,%1,%2,%3};" \
    : "+f"((d)[0]), "+f"((d)[1]), "+f"((d)[2]), "+f"((d)[3]) \
    : "r"((a)[0]), "r"((a)[1]), "r"((a)[2]), "r"((a)[3]), "r"((b)[0]), "r"((b)[1]))
#define CPA16(sa, gp) asm volatile("cp.async.cg.shared.global [%0],[%1],16;" :: "r"(sa), "l"(gp))
#define CPCOMMIT()    asm volatile("cp.async.commit_group;" ::: "memory")
#define CPWAIT1()     asm volatile("cp.async.wait_group 1;" ::: "memory")
#define CPWAIT0()     asm volatile("cp.async.wait_group 0;" ::: "memory")

// ---------------- init kernels (run once per launch, L1 flushed per launch) ----
__global__ void init_weights(
    const float* __restrict__ eWih0,
    const float* __restrict__ eWhh0, const float* __restrict__ eWih1, const float* __restrict__ eWhh1,
    const float* __restrict__ dWhh0, const float* __restrict__ dWih1, const float* __restrict__ dWhh1,
    const float* __restrict__ ebih0, const float* __restrict__ ebhh0,
    const float* __restrict__ ebih1, const float* __restrict__ ebhh1,
    const float* __restrict__ dbih0, const float* __restrict__ dbhh0,
    const float* __restrict__ dbih1, const float* __restrict__ dbhh1)
{
    const float* Wsrc[6] = {eWhh0, eWih1, eWhh1, dWhh0, dWih1, dWhh1};
    const long stride = (long)gridDim.x * blockDim.x;
    const long i0 = (long)blockIdx.x * blockDim.x + threadIdx.x;

    const long totW = 6L * NTL * 8 * BNR * KC;
    for (long i = i0; i < totW; i += stride) {
        int k = (int)(i % KC); long q = i / KC;
        int r = (int)(q % BNR); q /= BNR;
        int ch = (int)(q % 8); q /= 8;
        int nt = (int)(q % NTL); int ty = (int)(q / NTL);
        int g = r >> 5, jl = r & 31, j = nt * 32 + jl, kg = ch * KC + k;
        float v = Wsrc[ty][(size_t)(g * HD + j) * HD + kg];
        __nv_bfloat16 hi = __float2bfloat16(v);
        __nv_bfloat16 lo = __float2bfloat16(v - __bfloat162float(hi));
        int oe = offel(r, k);
        g_w[ty][nt][ch][0][oe] = hi;
        g_w[ty][nt][ch][1][oe] = lo;
    }
    // enc0 Wih (K=32): B1 = [Whi | Whi], B2 = [Wlo | 0]
    const long totX = (long)NTL * BNR * KC;
    for (long i = i0; i < totX; i += stride) {
        int k = (int)(i % KC); long q = i / KC;
        int r = (int)(q % BNR); int nt = (int)(q / BNR);
        int g = r >> 5, jl = r & 31, j = nt * 32 + jl, kk = k & 31;
        float v = eWih0[(size_t)(g * HD + j) * DIN + kk];
        __nv_bfloat16 hi = __float2bfloat16(v);
        __nv_bfloat16 lo = __float2bfloat16(v - __bfloat162float(hi));
        int oe = offel(r, k);
        g_wx[nt][0][oe] = hi;
        g_wx[nt][1][oe] = (k < 32) ? lo : __float2bfloat16(0.f);
    }
    const float* bi[4] = {ebih0, ebih1, dbih0, dbih1};
    const float* bh[4] = {ebhh0, ebhh1, dbhh0, dbhh1};
    for (long i = i0; i < 4 * HD; i += stride) {
        int tt = (int)(i / HD), j = (int)(i % HD);
        g_br[tt][j]  = bi[tt][j] + bh[tt][j];
        g_bz[tt][j]  = bi[tt][HD + j] + bh[tt][HD + j];
        g_bin[tt][j] = bi[tt][2 * HD + j];
        g_bhn[tt][j] = bh[tt][2 * HD + j];
    }
}

__global__ void init_x(const float* __restrict__ x)
{
    const long stride = (long)gridDim.x * blockDim.x;
    const long tot = (long)TSEQ * MT * BMR * KC;
    for (long i = (long)blockIdx.x * blockDim.x + threadIdx.x; i < tot; i += stride) {
        int k = (int)(i % KC); long q = i / KC;
        int r = (int)(q % BMR); q /= BMR;
        int mt = (int)(q % MT); int t = (int)(q / MT);
        int b = mt * BMR + r, c = k & 31;
        float v = x[((long)b * TSEQ + t) * DIN + c];
        __nv_bfloat16 hi = __float2bfloat16(v);
        __nv_bfloat16 val = (k < 32) ? hi : __float2bfloat16(v - __bfloat162float(hi));
        g_xbf[t][mt][offel(r, k)] = val;
    }
}

// ---------------- grid barrier ----------------
__device__ __forceinline__ void gbar()
{
    __syncthreads();
    if (threadIdx.x == 0) {
        __threadfence();
        unsigned gen = *(volatile unsigned*)&g_gen;
        unsigned t = atomicAdd(&g_cnt, 1u);
        if (t == NCTA - 1) {
            *(volatile unsigned*)&g_cnt = 0;
            __threadfence();
            *(volatile unsigned*)&g_gen = gen + 1;
        } else {
            while (*(volatile unsigned*)&g_gen == gen) __nanosleep(32);
        }
        __threadfence();
    }
    __syncthreads();
}

// ---------------- chunk compute (templated on mode for static reg indices) ----
// MODE 0: hidden GEMM, 3 products, tiles 0..11
// MODE 1: input  GEMM, 3 products, rz -> tiles 0..7, n -> 12..15
// MODE 2: x chunk, 2 products (A',B1)+(A',B2), rz -> 0..7, n -> 12..15
template<int MODE>
__device__ __forceinline__ void compute_chunk(uint32_t sbuf, int lane, int wid,
                                              float (&acc)[16][4])
{
    const uint32_t sA = sbuf, sAlo = sbuf + A_BYT;
    const uint32_t sB = sbuf + 2 * A_BYT, sBlo = sB + B_BYT;
    const int arow = wid * 16 + (lane & 7) + ((lane >> 3) & 1) * 8;
    const int akh  = (lane >> 4) * 8;
    const int blrow = lane & 7;
    const int bkh = ((lane >> 3) & 1) * 8;
#pragma unroll
    for (int kq = 0; kq < 4; kq++) {
        const int kb = kq * 16;
        uint32_t ahi[4], alo[4];
        const uint32_t aoff = 2u * (uint32_t)offel(arow, kb + akh);
        LDSM4(ahi, sA + aoff);
        if (MODE != 2) LDSM4(alo, sAlo + aoff);
#pragma unroll
        for (int t = 0; t < 12; t++) {
            uint32_t bhi[2], blo[2];
            const uint32_t boff = 2u * (uint32_t)offel(t * 8 + blrow, kb + bkh);
            LDSM2(bhi, sB + boff);
            LDSM2(blo, sBlo + boff);
            const int ai = (MODE == 0) ? t : (t < 8 ? t : t + 4);
            MMAB(acc[ai], ahi, bhi);
            if (MODE == 2) {
                MMAB(acc[ai], ahi, blo);
            } else {
                MMAB(acc[ai], alo, bhi);
                MMAB(acc[ai], ahi, blo);
            }
        }
    }
}

struct Ck { const char* A; const char* B; int mode; };

// ---------------- persistent kernel ----------------
__global__ void __launch_bounds__(256, 1) gru_tc(
    const float* __restrict__ dWih0,
    const float* __restrict__ outW, const float* __restrict__ outb,
    const float* __restrict__ dstart, float* __restrict__ out)
{
    extern __shared__ char smem[];
    const int tid = threadIdx.x, wid = tid >> 5, lane = tid & 31;
    const int mt = blockIdx.x >> 4, nt = blockIdx.x & 15;

    // ---- per-launch state init (deterministic across replays) ----
    {
        const long gs = (long)NCTA * 256;
        for (long i = (long)blockIdx.x * 256 + tid; i < (long)BATCH * HD; i += gs) {
            g_h1[0][i] = 0.f; g_h2[0][i] = 0.f;
        }
        uint32_t* z1 = (uint32_t*)&g_h1bf[0][0][0][0][0];
        uint32_t* z2 = (uint32_t*)&g_h2bf[0][0][0][0][0];
        const long nz = (long)MT * 8 * 2 * A_ELE / 2;
        for (long i = (long)blockIdx.x * 256 + tid; i < nz; i += gs) { z1[i] = 0; z2[i] = 0; }
        for (long i = (long)blockIdx.x * 256 + tid; i < BATCH; i += gs) g_y[i] = dstart[0];
    }
    gbar();

    float acc[16][4];

    auto load_chunk = [&](int bufidx, const Ck& c) {
        uint32_t dst = smem_u32(smem) + bufidx * BUF_BYTES;
        const int nA = (c.mode == 2 ? A_BYT : 2 * A_BYT) >> 4;
        for (int i = tid; i < nA; i += 256) CPA16(dst + i * 16, c.A + i * 16);
        const uint32_t bdst = dst + 2 * A_BYT;
        for (int i = tid; i < (2 * B_BYT) >> 4; i += 256) CPA16(bdst + i * 16, c.B + i * 16);
        CPCOMMIT();
    };

    auto run_cell = [&](const Ck* cks, int n) {
#pragma unroll
        for (int t = 0; t < 16; t++)
#pragma unroll
            for (int i = 0; i < 4; i++) acc[t][i] = 0.f;
        load_chunk(0, cks[0]);
        for (int i = 0; i < n; i++) {
            if (i + 1 < n) { load_chunk((i + 1) & 1, cks[i + 1]); CPWAIT1(); }
            else CPWAIT0();
            __syncthreads();
            const uint32_t sbuf = smem_u32(smem) + (i & 1) * BUF_BYTES;
            const int m = cks[i].mode;
            if (m == 0)      compute_chunk<0>(sbuf, lane, wid, acc);
            else if (m == 1) compute_chunk<1>(sbuf, lane, wid, acc);
            else             compute_chunk<2>(sbuf, lane, wid, acc);
            __syncthreads();
        }
    };

    // epilogue: gates + state update. dec0W != null => decoder layer0 scalar input.
    auto epilogue = [&](int bt, const float* hprev, float* hout,
                        char* hbfbase, const float* dec0W) {
        const int r0 = wid * 16 + (lane >> 2);
        const int cb = (lane & 3) * 2;
        const int kbase = (nt & 1) * 32;
#pragma unroll
        for (int rs = 0; rs < 2; rs++) {
            const int rloc = r0 + rs * 8;
            const int grow = mt * 128 + rloc;
            const float yy = dec0W ? __ldcg(&g_y[grow]) : 0.f;
#pragma unroll
            for (int tt = 0; tt < 4; tt++) {
#pragma unroll
                for (int e = 0; e < 2; e++) {
                    const int jl = tt * 8 + cb + e;
                    const int j = nt * 32 + jl;
                    const int ai = rs * 2 + e;
                    float rv = acc[tt][ai], zv = acc[4 + tt][ai];
                    float nh = acc[8 + tt][ai], ni = acc[12 + tt][ai];
                    if (dec0W) {
                        rv += yy * dec0W[j];
                        zv += yy * dec0W[HD + j];
                        ni  = yy * dec0W[2 * HD + j];
                    }
                    const float r = 1.f / (1.f + expf(-(rv + g_br[bt][j])));
                    const float z = 1.f / (1.f + expf(-(zv + g_bz[bt][j])));
                    const float n = tanhf(ni + g_bin[bt][j] + r * (nh + g_bhn[bt][j]));
                    const float hp = hprev[(size_t)grow * HD + j];
                    const float hv = n + z * (hp - n);
                    hout[(size_t)grow * HD + j] = hv;
                    __nv_bfloat16 hi = __float2bfloat16(hv);
                    __nv_bfloat16 lo = __float2bfloat16(hv - __bfloat162float(hi));
                    const int oe = offel(rloc, kbase + jl);
                    ((__nv_bfloat16*)hbfbase)[oe] = hi;
                    ((__nv_bfloat16*)(hbfbase + A_BYT))[oe] = lo;
                }
            }
        }
    };

    Ck cks[16];
    int p = 0;

    // ---------------- encoder: 512 steps ----------------
    for (int t = 0; t < TSEQ; t++) {
        // layer 0
        for (int c = 0; c < 8; c++)
            cks[c] = { (const char*)&g_h1bf[p][mt][c][0][0],
                       (const char*)&g_w[0][nt][c][0][0], 0 };
        cks[8] = { (const char*)&g_xbf[t][mt][0], (const char*)&g_wx[nt][0][0], 2 };
        run_cell(cks, 9);
        epilogue(0, g_h1[p], g_h1[1 - p], (char*)&g_h1bf[1 - p][mt][nt >> 1][0][0], nullptr);
        gbar();
        // layer 1
        for (int c = 0; c < 8; c++) {
            cks[c]     = { (const char*)&g_h2bf[p][mt][c][0][0],
                           (const char*)&g_w[2][nt][c][0][0], 0 };
            cks[8 + c] = { (const char*)&g_h1bf[1 - p][mt][c][0][0],
                           (const char*)&g_w[1][nt][c][0][0], 1 };
        }
        run_cell(cks, 16);
        epilogue(1, g_h2[p], g_h2[1 - p], (char*)&g_h2bf[1 - p][mt][nt >> 1][0][0], nullptr);
        gbar();
        p ^= 1;
    }

    // ---------------- decoder: 96 steps ----------------
    for (int s = 0; s < PLEN; s++) {
        // layer 0 (scalar input handled in epilogue)
        for (int c = 0; c < 8; c++)
            cks[c] = { (const char*)&g_h1bf[p][mt][c][0][0],
                       (const char*)&g_w[3][nt][c][0][0], 0 };
        run_cell(cks, 8);
        epilogue(2, g_h1[p], g_h1[1 - p], (char*)&g_h1bf[1 - p][mt][nt >> 1][0][0], dWih0);
        gbar();
        // layer 1
        for (int c = 0; c < 8; c++) {
            cks[c]     = { (const char*)&g_h2bf[p][mt][c][0][0],
                           (const char*)&g_w[5][nt][c][0][0], 0 };
            cks[8 + c] = { (const char*)&g_h1bf[1 - p][mt][c][0][0],
                           (const char*)&g_w[4][nt][c][0][0], 1 };
        }
        run_cell(cks, 16);
        epilogue(3, g_h2[p], g_h2[1 - p], (char*)&g_h2bf[1 - p][mt][nt >> 1][0][0], nullptr);
        gbar();
        // projection: 8 rows per CTA, one warp each (cross-CTA reads -> .cg)
        {
            const int row = blockIdx.x * 8 + wid;
            const float* hr = g_h2[1 - p] + (size_t)row * HD;
            float ss = 0.f;
#pragma unroll
            for (int q = 0; q < HD / 32; q++)
                ss += __ldcg(&hr[lane + 32 * q]) * outW[lane + 32 * q];
#pragma unroll
            for (int o = 16; o > 0; o >>= 1)
                ss += __shfl_xor_sync(0xffffffffu, ss, o);
            if (lane == 0) {
                const float v = ss + outb[0];
                g_y[row] = v;
                out[(size_t)row * PLEN + s] = v;
            }
        }
        gbar();
        p ^= 1;
    }
}

// ---------------------------------------------------------------------------
extern "C" void kernel_launch(void* const* d_in, const int* in_sizes, int n_in,
                              void* d_out, int out_size)
{
    const float* x      = (const float*)d_in[0];
    const float* eWih0  = (const float*)d_in[1];
    const float* eWhh0  = (const float*)d_in[2];
    const float* ebih0  = (const float*)d_in[3];
    const float* ebhh0  = (const float*)d_in[4];
    const float* eWih1  = (const float*)d_in[5];
    const float* eWhh1  = (const float*)d_in[6];
    const float* ebih1  = (const float*)d_in[7];
    const float* ebhh1  = (const float*)d_in[8];
    const float* dWih0  = (const float*)d_in[9];
    const float* dWhh0  = (const float*)d_in[10];
    const float* dbih0  = (const float*)d_in[11];
    const float* dbhh0  = (const float*)d_in[12];
    const float* dWih1  = (const float*)d_in[13];
    const float* dWhh1  = (const float*)d_in[14];
    const float* dbih1  = (const float*)d_in[15];
    const float* dbhh1  = (const float*)d_in[16];
    const float* outW   = (const float*)d_in[17];
    const float* outb   = (const float*)d_in[18];
    const float* dstart = (const float*)d_in[19];
    float* out = (float*)d_out;

    cudaFuncSetAttribute(gru_tc, cudaFuncAttributeMaxDynamicSharedMemorySize, SM_TOTAL);

    init_weights<<<1024, 256>>>(eWih0,
                                eWhh0, eWih1, eWhh1, dWhh0, dWih1, dWhh1,
                                ebih0, ebhh0, ebih1, ebhh1,
                                dbih0, dbhh0, dbih1, dbhh1);
    init_x<<<2048, 256>>>(x);
    gru_tc<<<NCTA, 256, SM_TOTAL>>>(dWih0, outW, outb, dstart, out);
}

// round 6
// speedup vs baseline: 2.6010x; 1.0285x over previous
#include <cuda_runtime.h>
#include <cuda_bf16.h>
#include <cstdint>
#include <cstddef>

// ---------------- problem dims ----------------
#define HD    512
#define BATCH 1024
#define TSEQ  512
#define PLEN  96
#define DIN   32

// ---------------- tiling ----------------
#define NCTA 128
#define MT   8          // m-tiles (BATCH/128)
#define NTL  16         // n-tiles (HD/32)
#define BMR  128        // batch rows per CTA
#define BNR  96         // gate rows of W per CTA (3 gates x 32)
#define KC   64         // k per chunk

#define A_ELE (BMR*KC)  // 8192
#define B_ELE (BNR*KC)  // 6144
#define A_BYT (A_ELE*2) // 16384
#define B_BYT (B_ELE*2) // 12288
#define BUF_BYTES (2*A_BYT + 2*B_BYT)   // 57344
#define SM_TOTAL  (2*BUF_BYTES)         // 114688

// ---------------- device globals (static scratch) ----------------
__device__ float g_h1[2][BATCH*HD];
__device__ float g_h2[2][BATCH*HD];
__device__ __align__(16) __nv_bfloat16 g_h1bf[2][MT][8][2][A_ELE];
__device__ __align__(16) __nv_bfloat16 g_h2bf[2][MT][8][2][A_ELE];
__device__ __align__(16) __nv_bfloat16 g_xbf[TSEQ][MT][A_ELE];     // [xhi|xlo] k64
__device__ __align__(16) __nv_bfloat16 g_w[6][NTL][8][2][B_ELE];   // 0:e0hh 1:e1ih 2:e1hh 3:d0hh 4:d1ih 5:d1hh
__device__ __align__(16) __nv_bfloat16 g_wx[NTL][2][B_ELE];        // enc0 Wih: B1=[Whi|Whi], B2=[Wlo|0]
__device__ float g_br[4][HD], g_bz[4][HD], g_bin[4][HD], g_bhn[4][HD];
__device__ float g_y[BATCH];
__device__ unsigned g_cnt, g_gen;

// ---------------- tile addressing (ldmatrix-friendly swizzle) ----------------
// rows of 64 bf16 (128B); 16B unit XOR-swizzled by row&7 -> conflict-free LDSM.
__host__ __device__ __forceinline__ int offel(int r, int k) {
    return r * 64 + ((((k >> 3) ^ (r & 7)) << 3) | (k & 7));
}

// ---------------- PTX helpers ----------------
__device__ __forceinline__ uint32_t smem_u32(const void* p) {
    uint32_t a;
    asm("{ .reg .u64 t; cvta.to.shared.u64 t, %1; cvt.u32.u64 %0, t; }" : "=r"(a) : "l"(p));
    return a;
}
#define LDSM4(r, addr) asm volatile("ldmatrix.sync.aligned.m8n8.x4.shared.b16 {%0,%1,%2,%3},[%4];" \
    : "=r"((r)[0]), "=r"((r)[1]), "=r"((r)[2]), "=r"((r)[3]) : "r"(addr))
#define MMAB(d, a, b0, b1) asm volatile( \
    "mma.sync.aligned.m16n8k16.row.col.f32.bf16.bf16.f32 {%0,%1,%2,%3},{%4,%5,%6,%7},{%8,%9},{%0,%1,%2,%3};" \
    : "+f"((d)[0]), "+f"((d)[1]), "+f"((d)[2]), "+f"((d)[3]) \
    : "r"((a)[0]), "r"((a)[1]), "r"((a)[2]), "r"((a)[3]), "r"(b0), "r"(b1))
#define CPA16(sa, gp) asm volatile("cp.async.cg.shared.global [%0],[%1],16;" :: "r"(sa), "l"(gp))
#define CPCOMMIT()    asm volatile("cp.async.commit_group;" ::: "memory")
#define CPWAIT1()     asm volatile("cp.async.wait_group 1;" ::: "memory")
#define CPWAIT0()     asm volatile("cp.async.wait_group 0;" ::: "memory")

// ---------------- init kernels ----------------
__global__ void init_weights(
    const float* __restrict__ eWih0,
    const float* __restrict__ eWhh0, const float* __restrict__ eWih1, const float* __restrict__ eWhh1,
    const float* __restrict__ dWhh0, const float* __restrict__ dWih1, const float* __restrict__ dWhh1,
    const float* __restrict__ ebih0, const float* __restrict__ ebhh0,
    const float* __restrict__ ebih1, const float* __restrict__ ebhh1,
    const float* __restrict__ dbih0, const float* __restrict__ dbhh0,
    const float* __restrict__ dbih1, const float* __restrict__ dbhh1)
{
    const float* Wsrc[6] = {eWhh0, eWih1, eWhh1, dWhh0, dWih1, dWhh1};
    const long stride = (long)gridDim.x * blockDim.x;
    const long i0 = (long)blockIdx.x * blockDim.x + threadIdx.x;

    const long totW = 6L * NTL * 8 * BNR * KC;
    for (long i = i0; i < totW; i += stride) {
        int k = (int)(i % KC); long q = i / KC;
        int r = (int)(q % BNR); q /= BNR;
        int ch = (int)(q % 8); q /= 8;
        int nt = (int)(q % NTL); int ty = (int)(q / NTL);
        int g = r >> 5, jl = r & 31, j = nt * 32 + jl, kg = ch * KC + k;
        float v = Wsrc[ty][(size_t)(g * HD + j) * HD + kg];
        __nv_bfloat16 hi = __float2bfloat16(v);
        __nv_bfloat16 lo = __float2bfloat16(v - __bfloat162float(hi));
        int oe = offel(r, k);
        g_w[ty][nt][ch][0][oe] = hi;
        g_w[ty][nt][ch][1][oe] = lo;
    }
    // enc0 Wih (K=32): B1 = [Whi | Whi], B2 = [Wlo | 0]
    const long totX = (long)NTL * BNR * KC;
    for (long i = i0; i < totX; i += stride) {
        int k = (int)(i % KC); long q = i / KC;
        int r = (int)(q % BNR); int nt = (int)(q / BNR);
        int g = r >> 5, jl = r & 31, j = nt * 32 + jl, kk = k & 31;
        float v = eWih0[(size_t)(g * HD + j) * DIN + kk];
        __nv_bfloat16 hi = __float2bfloat16(v);
        __nv_bfloat16 lo = __float2bfloat16(v - __bfloat162float(hi));
        int oe = offel(r, k);
        g_wx[nt][0][oe] = hi;
        g_wx[nt][1][oe] = (k < 32) ? lo : __float2bfloat16(0.f);
    }
    const float* bi[4] = {ebih0, ebih1, dbih0, dbih1};
    const float* bh[4] = {ebhh0, ebhh1, dbhh0, dbhh1};
    for (long i = i0; i < 4 * HD; i += stride) {
        int tt = (int)(i / HD), j = (int)(i % HD);
        g_br[tt][j]  = bi[tt][j] + bh[tt][j];
        g_bz[tt][j]  = bi[tt][HD + j] + bh[tt][HD + j];
        g_bin[tt][j] = bi[tt][2 * HD + j];
        g_bhn[tt][j] = bh[tt][2 * HD + j];
    }
}

__global__ void init_x(const float* __restrict__ x)
{
    const long stride = (long)gridDim.x * blockDim.x;
    const long tot = (long)TSEQ * MT * BMR * KC;
    for (long i = (long)blockIdx.x * blockDim.x + threadIdx.x; i < tot; i += stride) {
        int k = (int)(i % KC); long q = i / KC;
        int r = (int)(q % BMR); q /= BMR;
        int mt = (int)(q % MT); int t = (int)(q / MT);
        int b = mt * BMR + r, c = k & 31;
        float v = x[((long)b * TSEQ + t) * DIN + c];
        __nv_bfloat16 hi = __float2bfloat16(v);
        __nv_bfloat16 val = (k < 32) ? hi : __float2bfloat16(v - __bfloat162float(hi));
        g_xbf[t][mt][offel(r, k)] = val;
    }
}

// ---------------- grid barrier ----------------
__device__ __forceinline__ void gbar()
{
    __syncthreads();
    if (threadIdx.x == 0) {
        __threadfence();
        unsigned gen = *(volatile unsigned*)&g_gen;
        unsigned t = atomicAdd(&g_cnt, 1u);
        if (t == NCTA - 1) {
            *(volatile unsigned*)&g_cnt = 0;
            __threadfence();
            *(volatile unsigned*)&g_gen = gen + 1;
        } else {
            while (*(volatile unsigned*)&g_gen == gen) __nanosleep(32);
        }
        __threadfence();
    }
    __syncthreads();
}

// ---------------- chunk compute: 2D warp tiling 4m x 2n ----------------
// Warp (wm, wn): rows [wm*32, wm*32+32), cols = 3 gates x [wn*16, wn*16+16).
// MODE 0: hidden GEMM (3 products), n-gate -> aNH
// MODE 1: input  GEMM (3 products), n-gate -> aNI
// MODE 2: x chunk (2 products: A'*B1 + A'*B2), n-gate -> aNI
template<int MODE>
__device__ __forceinline__ void compute_chunk(
    uint32_t sbuf, int lane, int wm, int wn,
    float (&aR)[2][2][4], float (&aZ)[2][2][4],
    float (&aNH)[2][2][4], float (&aNI)[2][2][4])
{
    const uint32_t sA = sbuf, sAlo = sbuf + A_BYT;
    const uint32_t sB = sbuf + 2 * A_BYT, sBlo = sB + B_BYT;
    // A LDSM4 lane mapping: m0 rows0-7 klo, m1 rows8-15 klo, m2 rows0-7 khi, m3 rows8-15 khi
    const int a_row = wm * 32 + (lane & 7) + ((lane >> 3) & 1) * 8;
    const int a_kh  = (lane >> 4) * 8;
    // B LDSM4 lane mapping: m0 n0-7 klo, m1 n0-7 khi, m2 n8-15 klo, m3 n8-15 khi
    const int b_roff = (lane & 7) + ((lane >> 4) & 1) * 8;
    const int b_kh   = ((lane >> 3) & 1) * 8;

#pragma unroll
    for (int kq = 0; kq < 4; kq++) {
        const int kb = kq * 16;
        uint32_t ahi[2][4], alo[2][4];
#pragma unroll
        for (int mtl = 0; mtl < 2; mtl++) {
            const uint32_t ao = 2u * (uint32_t)offel(a_row + mtl * 16, kb + a_kh);
            LDSM4(ahi[mtl], sA + ao);
            if (MODE != 2) LDSM4(alo[mtl], sAlo + ao);
        }
#pragma unroll
        for (int g = 0; g < 3; g++) {
            const uint32_t bo = 2u * (uint32_t)offel(g * 32 + wn * 16 + b_roff, kb + b_kh);
            uint32_t bhi[4], blo[4];
            LDSM4(bhi, sB + bo);
            LDSM4(blo, sBlo + bo);
#pragma unroll
            for (int mtl = 0; mtl < 2; mtl++) {
#pragma unroll
                for (int n8 = 0; n8 < 2; n8++) {
                    float* dst = (g == 0) ? aR[mtl][n8]
                               : (g == 1) ? aZ[mtl][n8]
                               : (MODE == 0 ? aNH[mtl][n8] : aNI[mtl][n8]);
                    MMAB(dst, ahi[mtl], bhi[2 * n8], bhi[2 * n8 + 1]);
                    if (MODE == 2) {
                        MMAB(dst, ahi[mtl], blo[2 * n8], blo[2 * n8 + 1]);
                    } else {
                        MMAB(dst, alo[mtl], bhi[2 * n8], bhi[2 * n8 + 1]);
                        MMAB(dst, ahi[mtl], blo[2 * n8], blo[2 * n8 + 1]);
                    }
                }
            }
        }
    }
}

struct Ck { const char* A; const char* B; int mode; };

// ---------------- persistent kernel ----------------
__global__ void __launch_bounds__(256, 1) gru_tc(
    const float* __restrict__ dWih0,
    const float* __restrict__ outW, const float* __restrict__ outb,
    const float* __restrict__ dstart, float* __restrict__ out)
{
    extern __shared__ char smem[];
    const int tid = threadIdx.x, wid = tid >> 5, lane = tid & 31;
    const int wm = wid & 3, wn = wid >> 2;
    const int mt = blockIdx.x >> 4, nt = blockIdx.x & 15;

    // ---- per-launch state init ----
    {
        const long gs = (long)NCTA * 256;
        for (long i = (long)blockIdx.x * 256 + tid; i < (long)BATCH * HD; i += gs) {
            g_h1[0][i] = 0.f; g_h2[0][i] = 0.f;
        }
        uint32_t* z1 = (uint32_t*)&g_h1bf[0][0][0][0][0];
        uint32_t* z2 = (uint32_t*)&g_h2bf[0][0][0][0][0];
        const long nz = (long)MT * 8 * 2 * A_ELE / 2;
        for (long i = (long)blockIdx.x * 256 + tid; i < nz; i += gs) { z1[i] = 0; z2[i] = 0; }
        for (long i = (long)blockIdx.x * 256 + tid; i < BATCH; i += gs) g_y[i] = dstart[0];
    }
    gbar();

    float aR[2][2][4], aZ[2][2][4], aNH[2][2][4], aNI[2][2][4];

    auto zero_acc = [&]() {
#pragma unroll
        for (int a = 0; a < 2; a++)
#pragma unroll
            for (int b = 0; b < 2; b++)
#pragma unroll
                for (int c = 0; c < 4; c++) {
                    aR[a][b][c] = 0.f; aZ[a][b][c] = 0.f;
                    aNH[a][b][c] = 0.f; aNI[a][b][c] = 0.f;
                }
    };

    auto load_chunk = [&](int bufidx, const Ck& c) {
        uint32_t dst = smem_u32(smem) + bufidx * BUF_BYTES;
        const int nA = (c.mode == 2 ? A_BYT : 2 * A_BYT) >> 4;
        for (int i = tid; i < nA; i += 256) CPA16(dst + i * 16, c.A + i * 16);
        const uint32_t bdst = dst + 2 * A_BYT;
        for (int i = tid; i < (2 * B_BYT) >> 4; i += 256) CPA16(bdst + i * 16, c.B + i * 16);
        CPCOMMIT();
    };

    auto run_seg = [&](const Ck* cks, int n) {
        load_chunk(0, cks[0]);
        for (int i = 0; i < n; i++) {
            if (i + 1 < n) { load_chunk((i + 1) & 1, cks[i + 1]); CPWAIT1(); }
            else CPWAIT0();
            __syncthreads();
            const uint32_t sbuf = smem_u32(smem) + (i & 1) * BUF_BYTES;
            const int m = cks[i].mode;
            if (m == 0)      compute_chunk<0>(sbuf, lane, wm, wn, aR, aZ, aNH, aNI);
            else if (m == 1) compute_chunk<1>(sbuf, lane, wm, wn, aR, aZ, aNH, aNI);
            else             compute_chunk<2>(sbuf, lane, wm, wn, aR, aZ, aNH, aNI);
            __syncthreads();
        }
    };

    // epilogue: gates + state update. dec0W != null => decoder layer0 scalar input.
    auto epilogue = [&](int bt, const float* hprev, float* hout,
                        char* hbfbase, const float* dec0W) {
        const int qr = lane >> 2, qc = lane & 3;
        const int kbase = (nt & 1) * 32;
#pragma unroll
        for (int mtl = 0; mtl < 2; mtl++) {
#pragma unroll
            for (int fr = 0; fr < 2; fr++) {
                const int rloc = wm * 32 + mtl * 16 + qr + fr * 8;
                const int grow = mt * 128 + rloc;
                const float yy = dec0W ? __ldcg(&g_y[grow]) : 0.f;
#pragma unroll
                for (int n8 = 0; n8 < 2; n8++) {
#pragma unroll
                    for (int e = 0; e < 2; e++) {
                        const int jl = wn * 16 + n8 * 8 + qc * 2 + e;
                        const int j = nt * 32 + jl;
                        const int ci = fr * 2 + e;
                        float rv = aR[mtl][n8][ci], zv = aZ[mtl][n8][ci];
                        float nh = aNH[mtl][n8][ci], ni = aNI[mtl][n8][ci];
                        if (dec0W) {
                            rv += yy * dec0W[j];
                            zv += yy * dec0W[HD + j];
                            ni += yy * dec0W[2 * HD + j];
                        }
                        const float r = 1.f / (1.f + __expf(-(rv + g_br[bt][j])));
                        const float z = 1.f / (1.f + __expf(-(zv + g_bz[bt][j])));
                        const float n = tanhf(ni + g_bin[bt][j] + r * (nh + g_bhn[bt][j]));
                        const float hp = hprev[(size_t)grow * HD + j];
                        const float hv = n + z * (hp - n);
                        hout[(size_t)grow * HD + j] = hv;
                        __nv_bfloat16 hi = __float2bfloat16(hv);
                        __nv_bfloat16 lo = __float2bfloat16(hv - __bfloat162float(hi));
                        const int oe = offel(rloc, kbase + jl);
                        ((__nv_bfloat16*)hbfbase)[oe] = hi;
                        ((__nv_bfloat16*)(hbfbase + A_BYT))[oe] = lo;
                    }
                }
            }
        }
    };

    Ck ckA[9], ckB[8];
    int p = 0;

    // ---------------- encoder: 512 steps ----------------
    for (int t = 0; t < TSEQ; t++) {
        // layer 0: 8 hidden chunks + x chunk
        for (int c = 0; c < 8; c++)
            ckA[c] = { (const char*)&g_h1bf[p][mt][c][0][0],
                       (const char*)&g_w[0][nt][c][0][0], 0 };
        ckA[8] = { (const char*)&g_xbf[t][mt][0], (const char*)&g_wx[nt][0][0], 2 };
        zero_acc();
        run_seg(ckA, 9);
        epilogue(0, g_h1[p], g_h1[1 - p], (char*)&g_h1bf[1 - p][mt][nt >> 1][0][0], nullptr);
        // layer 1: hidden GEMM first (independent of new h1), then gbar, then input GEMM
        for (int c = 0; c < 8; c++) {
            ckA[c] = { (const char*)&g_h2bf[p][mt][c][0][0],
                       (const char*)&g_w[2][nt][c][0][0], 0 };
            ckB[c] = { (const char*)&g_h1bf[1 - p][mt][c][0][0],
                       (const char*)&g_w[1][nt][c][0][0], 1 };
        }
        zero_acc();
        run_seg(ckA, 8);
        gbar();                       // h1 writes now visible grid-wide
        run_seg(ckB, 8);
        epilogue(1, g_h2[p], g_h2[1 - p], (char*)&g_h2bf[1 - p][mt][nt >> 1][0][0], nullptr);
        gbar();
        p ^= 1;
    }

    // ---------------- decoder: 96 steps ----------------
    for (int s = 0; s < PLEN; s++) {
        // layer 0 (scalar input in epilogue)
        for (int c = 0; c < 8; c++)
            ckA[c] = { (const char*)&g_h1bf[p][mt][c][0][0],
                       (const char*)&g_w[3][nt][c][0][0], 0 };
        zero_acc();
        run_seg(ckA, 8);
        epilogue(2, g_h1[p], g_h1[1 - p], (char*)&g_h1bf[1 - p][mt][nt >> 1][0][0], dWih0);
        // layer 1
        for (int c = 0; c < 8; c++) {
            ckA[c] = { (const char*)&g_h2bf[p][mt][c][0][0],
                       (const char*)&g_w[5][nt][c][0][0], 0 };
            ckB[c] = { (const char*)&g_h1bf[1 - p][mt][c][0][0],
                       (const char*)&g_w[4][nt][c][0][0], 1 };
        }
        zero_acc();
        run_seg(ckA, 8);
        gbar();
        run_seg(ckB, 8);
        epilogue(3, g_h2[p], g_h2[1 - p], (char*)&g_h2bf[1 - p][mt][nt >> 1][0][0], nullptr);
        gbar();
        // projection: 8 rows per CTA, one warp each
        {
            const int row = blockIdx.x * 8 + wid;
            const float* hr = g_h2[1 - p] + (size_t)row * HD;
            float ss = 0.f;
#pragma unroll
            for (int q = 0; q < HD / 32; q++)
                ss += __ldcg(&hr[lane + 32 * q]) * outW[lane + 32 * q];
#pragma unroll
            for (int o = 16; o > 0; o >>= 1)
                ss += __shfl_xor_sync(0xffffffffu, ss, o);
            if (lane == 0) {
                const float v = ss + outb[0];
                g_y[row] = v;
                out[(size_t)row * PLEN + s] = v;
            }
        }
        gbar();
        p ^= 1;
    }
}

// ---------------------------------------------------------------------------
extern "C" void kernel_launch(void* const* d_in, const int* in_sizes, int n_in,
                              void* d_out, int out_size)
{
    const float* x      = (const float*)d_in[0];
    const float* eWih0  = (const float*)d_in[1];
    const float* eWhh0  = (const float*)d_in[2];
    const float* ebih0  = (const float*)d_in[3];
    const float* ebhh0  = (const float*)d_in[4];
    const float* eWih1  = (const float*)d_in[5];
    const float* eWhh1  = (const float*)d_in[6];
    const float* ebih1  = (const float*)d_in[7];
    const float* ebhh1  = (const float*)d_in[8];
    const float* dWih0  = (const float*)d_in[9];
    const float* dWhh0  = (const float*)d_in[10];
    const float* dbih0  = (const float*)d_in[11];
    const float* dbhh0  = (const float*)d_in[12];
    const float* dWih1  = (const float*)d_in[13];
    const float* dWhh1  = (const float*)d_in[14];
    const float* dbih1  = (const float*)d_in[15];
    const float* dbhh1  = (const float*)d_in[16];
    const float* outW   = (const float*)d_in[17];
    const float* outb   = (const float*)d_in[18];
    const float* dstart = (const float*)d_in[19];
    float* out = (float*)d_out;

    cudaFuncSetAttribute(gru_tc, cudaFuncAttributeMaxDynamicSharedMemorySize, SM_TOTAL);

    init_weights<<<1024, 256>>>(eWih0,
                                eWhh0, eWih1, eWhh1, dWhh0, dWih1, dWhh1,
                                ebih0, ebhh0, ebih1, ebhh1,
                                dbih0, dbhh0, dbih1, dbhh1);
    init_x<<<2048, 256>>>(x);
    gru_tc<<<NCTA, 256, SM_TOTAL>>>(dWih0, outW, outb, dstart, out);
}